// round 1
// baseline (speedup 1.0000x reference)
#include <cuda_runtime.h>
#include <math.h>

#define Bc 8
#define Sc 1024
#define Hc 8
#define Dc 64
#define DMc 512
#define NTOT (Bc*Hc*Sc*Dc)   // 4,194,304

// ---- scratch (device globals; no allocations allowed) ----
__device__ float g_q1[NTOT];
__device__ float g_q2[NTOT];
__device__ float g_gate[NTOT];   // (B,H,S,D)
__device__ float g_k1[NTOT];
__device__ float g_k2[NTOT];
__device__ float g_v[NTOT];      // (B,H,S,D)
__device__ float g_attn[NTOT];   // (B,S,H,D)
__device__ float g_mean[Bc*8];
__device__ float g_rstd[Bc*8];

// ============================================================
// Projection GEMM: C[8192 x N] = A[8192 x 512] @ W[512 x N] + bias,
// scattered into per-head split buffers laid out (B,H,S,D).
// mode 0: q (N=1536, perHead=192) -> q1,q2,gate
// mode 1: k (N=1024, perHead=128) -> k1,k2
// mode 2: v (N=512,  perHead=64)  -> v
// ============================================================
__global__ __launch_bounds__(256)
void proj_kernel(const float* __restrict__ A, const float* __restrict__ W,
                 const float* __restrict__ bias, int N, int perHead, int mode)
{
    __shared__ float As[16][65];
    __shared__ float Ws[16][65];

    const int K  = DMc;
    const int n0 = blockIdx.x * 64;
    const int m0 = blockIdx.y * 64;
    const int tid = threadIdx.x;
    const int ty = tid >> 4, tx = tid & 15;

    float* o0; float* o1; float* o2;
    if (mode == 0)      { o0 = g_q1; o1 = g_q2; o2 = g_gate; }
    else if (mode == 1) { o0 = g_k1; o1 = g_k2; o2 = g_k2; }
    else                { o0 = g_v;  o1 = g_v;  o2 = g_v;  }

    float acc[4][4] = {};

    const int ar = tid >> 2, ak4 = tid & 3;
    const int wr = tid >> 4, wc4 = tid & 15;

    for (int kt = 0; kt < K; kt += 16) {
        float4 av = *(const float4*)(A + (size_t)(m0 + ar) * K + kt + ak4 * 4);
        float4 wv = *(const float4*)(W + (size_t)(kt + wr) * N + n0 + wc4 * 4);
        As[ak4*4+0][ar] = av.x; As[ak4*4+1][ar] = av.y;
        As[ak4*4+2][ar] = av.z; As[ak4*4+3][ar] = av.w;
        Ws[wr][wc4*4+0] = wv.x; Ws[wr][wc4*4+1] = wv.y;
        Ws[wr][wc4*4+2] = wv.z; Ws[wr][wc4*4+3] = wv.w;
        __syncthreads();
        #pragma unroll
        for (int k = 0; k < 16; k++) {
            float a[4], b[4];
            #pragma unroll
            for (int i = 0; i < 4; i++) a[i] = As[k][ty*4+i];
            #pragma unroll
            for (int j = 0; j < 4; j++) b[j] = Ws[k][tx*4+j];
            #pragma unroll
            for (int i = 0; i < 4; i++)
                #pragma unroll
                for (int j = 0; j < 4; j++)
                    acc[i][j] += a[i] * b[j];
        }
        __syncthreads();
    }

    const int c0  = n0 + tx * 4;
    const int h   = c0 / perHead;
    const int r   = c0 % perHead;
    const int seg = r >> 6;
    const int d   = r & 63;
    float* dst = (seg == 0) ? o0 : ((seg == 1) ? o1 : o2);
    float4 bv4;
    bv4.x = bias[c0+0]; bv4.y = bias[c0+1]; bv4.z = bias[c0+2]; bv4.w = bias[c0+3];

    #pragma unroll
    for (int i = 0; i < 4; i++) {
        int m  = m0 + ty*4 + i;
        int bb = m >> 10, s = m & 1023;
        float4 v;
        v.x = acc[i][0] + bv4.x; v.y = acc[i][1] + bv4.y;
        v.z = acc[i][2] + bv4.z; v.w = acc[i][3] + bv4.w;
        *(float4*)(dst + (size_t)(((bb*Hc)+h)*Sc + s)*Dc + d) = v;
    }
}

// ============================================================
// Flash-style attention with TWO online softmaxes:
//   O = softmax(Q1 K1^T/8) V  -  lam * softmax(Q2 K2^T/8) V
// 64x64 query tile per block, 256 threads, fp32.
// Writes output in (B,S,H,D) layout for the norm stage.
// ============================================================
#define TS(p, rr, cc) p[(rr)*65 + (cc)]

__global__ __launch_bounds__(256)
void attn_kernel(const float* __restrict__ lam_p)
{
    extern __shared__ float sm[];
    float* Q1s = sm;
    float* Q2s = Q1s + 64*65;
    float* K1s = Q2s + 64*65;
    float* K2s = K1s + 64*65;
    float* Vs  = K2s + 64*65;
    float* S1s = Vs  + 64*65;
    float* S2s = S1s + 64*65;
    float* stm1 = S2s + 64*65;
    float* stl1 = stm1 + 64;
    float* stm2 = stl1 + 64;
    float* stl2 = stm2 + 64;
    float* stsc1 = stl2 + 64;
    float* stsc2 = stsc1 + 64;

    const int q0 = blockIdx.x * 64;
    const int h  = blockIdx.y;
    const int b  = blockIdx.z;
    const int tid = threadIdx.x;
    const int ty = tid >> 4, tx = tid & 15;

    const size_t headOff = (size_t)(b*Hc + h) * Sc * Dc;
    const float* q1g = g_q1 + headOff + (size_t)q0 * Dc;
    const float* q2g = g_q2 + headOff + (size_t)q0 * Dc;
    const float* k1g = g_k1 + headOff;
    const float* k2g = g_k2 + headOff;
    const float* vg  = g_v  + headOff;

    // load Q tiles (64x64)
    const int lr = tid >> 2;
    const int lc = (tid & 3) * 16;
    #pragma unroll
    for (int c = 0; c < 16; c += 4) {
        float4 v1 = *(const float4*)(q1g + lr*Dc + lc + c);
        TS(Q1s, lr, lc+c+0) = v1.x; TS(Q1s, lr, lc+c+1) = v1.y;
        TS(Q1s, lr, lc+c+2) = v1.z; TS(Q1s, lr, lc+c+3) = v1.w;
        float4 v2 = *(const float4*)(q2g + lr*Dc + lc + c);
        TS(Q2s, lr, lc+c+0) = v2.x; TS(Q2s, lr, lc+c+1) = v2.y;
        TS(Q2s, lr, lc+c+2) = v2.z; TS(Q2s, lr, lc+c+3) = v2.w;
    }
    if (tid < 64) {
        stm1[tid] = -1e30f; stl1[tid] = 0.0f;
        stm2[tid] = -1e30f; stl2[tid] = 0.0f;
    }

    float O1[4][4] = {}, O2[4][4] = {};
    __syncthreads();

    for (int kt = 0; kt < Sc; kt += 64) {
        // load K1,K2,V tile (rows kt..kt+63)
        const float* kp1 = k1g + (size_t)kt * Dc;
        const float* kp2 = k2g + (size_t)kt * Dc;
        const float* vp  = vg  + (size_t)kt * Dc;
        #pragma unroll
        for (int c = 0; c < 16; c += 4) {
            float4 v1 = *(const float4*)(kp1 + lr*Dc + lc + c);
            TS(K1s, lr, lc+c+0) = v1.x; TS(K1s, lr, lc+c+1) = v1.y;
            TS(K1s, lr, lc+c+2) = v1.z; TS(K1s, lr, lc+c+3) = v1.w;
            float4 v2 = *(const float4*)(kp2 + lr*Dc + lc + c);
            TS(K2s, lr, lc+c+0) = v2.x; TS(K2s, lr, lc+c+1) = v2.y;
            TS(K2s, lr, lc+c+2) = v2.z; TS(K2s, lr, lc+c+3) = v2.w;
            float4 v3 = *(const float4*)(vp + lr*Dc + lc + c);
            TS(Vs, lr, lc+c+0) = v3.x; TS(Vs, lr, lc+c+1) = v3.y;
            TS(Vs, lr, lc+c+2) = v3.z; TS(Vs, lr, lc+c+3) = v3.w;
        }
        __syncthreads();

        // S = Q K^T * 0.125 (both score matrices)
        {
            float s1a[4][4] = {}, s2a[4][4] = {};
            #pragma unroll 4
            for (int dd = 0; dd < 64; dd++) {
                float a1[4], b1[4], a2[4], b2[4];
                #pragma unroll
                for (int i = 0; i < 4; i++) { a1[i] = TS(Q1s, 4*ty+i, dd); a2[i] = TS(Q2s, 4*ty+i, dd); }
                #pragma unroll
                for (int j = 0; j < 4; j++) { b1[j] = TS(K1s, 4*tx+j, dd); b2[j] = TS(K2s, 4*tx+j, dd); }
                #pragma unroll
                for (int i = 0; i < 4; i++)
                    #pragma unroll
                    for (int j = 0; j < 4; j++) {
                        s1a[i][j] += a1[i] * b1[j];
                        s2a[i][j] += a2[i] * b2[j];
                    }
            }
            #pragma unroll
            for (int i = 0; i < 4; i++)
                #pragma unroll
                for (int j = 0; j < 4; j++) {
                    TS(S1s, 4*ty+i, 4*tx+j) = s1a[i][j] * 0.125f;
                    TS(S2s, 4*ty+i, 4*tx+j) = s2a[i][j] * 0.125f;
                }
        }
        __syncthreads();

        // online softmax update for both score tiles
        {
            const int row  = tid >> 2;
            const int base = (tid & 3) * 16;

            // --- softmax 1 ---
            float mx = -1e30f;
            #pragma unroll
            for (int c = 0; c < 16; c++) mx = fmaxf(mx, TS(S1s, row, base+c));
            mx = fmaxf(mx, __shfl_xor_sync(0xffffffffu, mx, 1));
            mx = fmaxf(mx, __shfl_xor_sync(0xffffffffu, mx, 2));
            float mold = stm1[row];
            float mnew = fmaxf(mold, mx);
            float sum = 0.0f;
            #pragma unroll
            for (int c = 0; c < 16; c++) {
                float p = __expf(TS(S1s, row, base+c) - mnew);
                TS(S1s, row, base+c) = p;
                sum += p;
            }
            sum += __shfl_xor_sync(0xffffffffu, sum, 1);
            sum += __shfl_xor_sync(0xffffffffu, sum, 2);
            if ((tid & 3) == 0) {
                float scl = __expf(mold - mnew);
                stsc1[row] = scl;
                stl1[row] = stl1[row] * scl + sum;
                stm1[row] = mnew;
            }

            // --- softmax 2 ---
            mx = -1e30f;
            #pragma unroll
            for (int c = 0; c < 16; c++) mx = fmaxf(mx, TS(S2s, row, base+c));
            mx = fmaxf(mx, __shfl_xor_sync(0xffffffffu, mx, 1));
            mx = fmaxf(mx, __shfl_xor_sync(0xffffffffu, mx, 2));
            mold = stm2[row];
            mnew = fmaxf(mold, mx);
            sum = 0.0f;
            #pragma unroll
            for (int c = 0; c < 16; c++) {
                float p = __expf(TS(S2s, row, base+c) - mnew);
                TS(S2s, row, base+c) = p;
                sum += p;
            }
            sum += __shfl_xor_sync(0xffffffffu, sum, 1);
            sum += __shfl_xor_sync(0xffffffffu, sum, 2);
            if ((tid & 3) == 0) {
                float scl = __expf(mold - mnew);
                stsc2[row] = scl;
                stl2[row] = stl2[row] * scl + sum;
                stm2[row] = mnew;
            }
        }
        __syncthreads();

        // O rescale + O += P V
        {
            float f1[4], f2[4];
            #pragma unroll
            for (int i = 0; i < 4; i++) { f1[i] = stsc1[4*ty+i]; f2[i] = stsc2[4*ty+i]; }
            #pragma unroll
            for (int i = 0; i < 4; i++)
                #pragma unroll
                for (int c = 0; c < 4; c++) { O1[i][c] *= f1[i]; O2[i][c] *= f2[i]; }

            #pragma unroll 4
            for (int jj = 0; jj < 64; jj++) {
                float vv[4], p1[4], p2[4];
                #pragma unroll
                for (int c = 0; c < 4; c++) vv[c] = TS(Vs, jj, 4*tx+c);
                #pragma unroll
                for (int i = 0; i < 4; i++) { p1[i] = TS(S1s, 4*ty+i, jj); p2[i] = TS(S2s, 4*ty+i, jj); }
                #pragma unroll
                for (int i = 0; i < 4; i++)
                    #pragma unroll
                    for (int c = 0; c < 4; c++) {
                        O1[i][c] += p1[i] * vv[c];
                        O2[i][c] += p2[i] * vv[c];
                    }
            }
        }
        __syncthreads();
    }

    // combine: O = O1/l1 - lam*O2/l2, write to (B,S,H,D)
    const float lam = lam_p[0];
    #pragma unroll
    for (int i = 0; i < 4; i++) {
        int rr = 4*ty + i;
        float i1 = 1.0f / stl1[rr];
        float i2 = lam  / stl2[rr];
        int s = q0 + rr;
        float4 v;
        v.x = O1[i][0]*i1 - O2[i][0]*i2;
        v.y = O1[i][1]*i1 - O2[i][1]*i2;
        v.z = O1[i][2]*i1 - O2[i][2]*i2;
        v.w = O1[i][3]*i1 - O2[i][3]*i2;
        *(float4*)(g_attn + (size_t)((b*Sc + s)*Hc + h)*Dc + 4*tx) = v;
    }
}

// ============================================================
// Group statistics: per (b, j) where d = j*8 + i,
// mean/var over (s, h, i) -> 65536 elements per group.
// ============================================================
__global__ __launch_bounds__(256)
void stats_kernel()
{
    const int b = blockIdx.x >> 3;
    const int j = blockIdx.x & 7;
    const int tid = threadIdx.x;
    double s = 0.0, sq = 0.0;
    const float* base = g_attn + (size_t)b*Sc*Hc*Dc + j*8;
    for (int t = tid; t < Sc*Hc; t += 256) {
        const float* p = base + (size_t)t * 64;
        #pragma unroll
        for (int i = 0; i < 8; i++) {
            float x = p[i];
            s  += (double)x;
            sq += (double)x * (double)x;
        }
    }
    __shared__ double ss[256], sqq[256];
    ss[tid] = s; sqq[tid] = sq;
    __syncthreads();
    for (int o = 128; o > 0; o >>= 1) {
        if (tid < o) { ss[tid] += ss[tid+o]; sqq[tid] += sqq[tid+o]; }
        __syncthreads();
    }
    if (tid == 0) {
        double mean = ss[0] / 65536.0;
        double var  = sqq[0] / 65536.0 - mean * mean;
        g_mean[blockIdx.x] = (float)mean;
        g_rstd[blockIdx.x] = (float)(1.0 / sqrt(var + 1e-3));
    }
}

// ============================================================
// Final: normalize, gamma/beta, *(1-lambda_init), *sigmoid(gate)
// ============================================================
__global__ __launch_bounds__(256)
void final_kernel(const float* __restrict__ gamma, const float* __restrict__ beta,
                  const float* __restrict__ li_p, float* __restrict__ out)
{
    const int idx = (blockIdx.x * 256 + threadIdx.x) * 4;
    const int d = idx & 63;
    const int h = (idx >> 6) & 7;
    const int s = (idx >> 9) & 1023;
    const int b = idx >> 19;
    const int j = d >> 3;
    const float mean = g_mean[b*8+j];
    const float rstd = g_rstd[b*8+j];
    const float li = 1.0f - li_p[0];
    float4 a  = *(const float4*)(g_attn + idx);
    float4 g  = *(const float4*)(g_gate + (size_t)((b*Hc+h)*Sc + s)*Dc + d);
    float4 gm = *(const float4*)(gamma + d);
    float4 bt = *(const float4*)(beta + d);
    float4 o;
    o.x = ((a.x-mean)*rstd*gm.x + bt.x) * li * (1.0f/(1.0f+__expf(-g.x)));
    o.y = ((a.y-mean)*rstd*gm.y + bt.y) * li * (1.0f/(1.0f+__expf(-g.y)));
    o.z = ((a.z-mean)*rstd*gm.z + bt.z) * li * (1.0f/(1.0f+__expf(-g.z)));
    o.w = ((a.w-mean)*rstd*gm.w + bt.w) * li * (1.0f/(1.0f+__expf(-g.w)));
    *(float4*)(out + idx) = o;
}

// ============================================================
extern "C" void kernel_launch(void* const* d_in, const int* in_sizes, int n_in,
                              void* d_out, int out_size)
{
    const float* query  = (const float*)d_in[0];
    const float* key    = (const float*)d_in[1];
    const float* values = (const float*)d_in[2];
    const float* Wq = (const float*)d_in[3];
    const float* bq = (const float*)d_in[4];
    const float* Wk = (const float*)d_in[5];
    const float* bk = (const float*)d_in[6];
    const float* Wv = (const float*)d_in[7];
    const float* bv = (const float*)d_in[8];
    const float* gamma = (const float*)d_in[9];
    const float* beta  = (const float*)d_in[10];
    const float* lam   = (const float*)d_in[11];
    const float* lambda_init = (const float*)d_in[12];
    float* out = (float*)d_out;

    const int attn_smem = (7*64*65 + 6*64) * (int)sizeof(float);  // 118016 B
    cudaFuncSetAttribute(attn_kernel, cudaFuncAttributeMaxDynamicSharedMemorySize, attn_smem);

    proj_kernel<<<dim3(24, 128), 256>>>(query,  Wq, bq, 1536, 192, 0);
    proj_kernel<<<dim3(16, 128), 256>>>(key,    Wk, bk, 1024, 128, 1);
    proj_kernel<<<dim3(8, 128),  256>>>(values, Wv, bv,  512,  64, 2);
    attn_kernel<<<dim3(16, 8, 8), 256, attn_smem>>>(lam);
    stats_kernel<<<64, 256>>>();
    final_kernel<<<NTOT/1024, 256>>>(gamma, beta, lambda_init, out);
}

// round 3
// speedup vs baseline: 1.3683x; 1.3683x over previous
#include <cuda_runtime.h>
#include <cuda_bf16.h>
#include <math.h>
#include <stdint.h>

#define Bc 8
#define Sc 1024
#define Hc 8
#define Dc 64
#define DMc 512
#define NTOT (Bc*Hc*Sc*Dc)   // 4,194,304

// ---- scratch (device globals; no allocations allowed) ----
__device__ float g_q1[NTOT];
__device__ float g_q2[NTOT];
__device__ float g_gate[NTOT];   // (B,H,S,D)
__device__ float g_k1[NTOT];
__device__ float g_k2[NTOT];
__device__ float g_v[NTOT];      // (B,H,S,D)
__device__ float g_attn[NTOT];   // (B,S,H,D)
__device__ float g_mean[Bc*8];
__device__ float g_rstd[Bc*8];

// bf16 hi/lo split operands for tensor-core projection GEMMs
__device__ __align__(16) __nv_bfloat16 g_Ahi[3][8192*512];
__device__ __align__(16) __nv_bfloat16 g_Alo[3][8192*512];
__device__ __align__(16) __nv_bfloat16 g_Whi[3072*512];   // W^T, [N][K] layout
__device__ __align__(16) __nv_bfloat16 g_Wlo[3072*512];

// ============================================================
// helpers: ldmatrix + mma.sync (bf16, HMMA path — sm_103 baseline)
// ============================================================
__device__ __forceinline__ uint32_t smem_u32(const void* p) {
    uint32_t a;
    asm("{ .reg .u64 t; cvta.to.shared.u64 t, %1; cvt.u32.u64 %0, t; }" : "=r"(a) : "l"(p));
    return a;
}
__device__ __forceinline__ void ldsm_x4(uint32_t* r, uint32_t addr) {
    asm volatile("ldmatrix.sync.aligned.m8n8.x4.shared.b16 {%0,%1,%2,%3}, [%4];"
                 : "=r"(r[0]), "=r"(r[1]), "=r"(r[2]), "=r"(r[3]) : "r"(addr));
}
__device__ __forceinline__ void ldsm_x2(uint32_t* r, uint32_t addr) {
    asm volatile("ldmatrix.sync.aligned.m8n8.x2.shared.b16 {%0,%1}, [%2];"
                 : "=r"(r[0]), "=r"(r[1]) : "r"(addr));
}
__device__ __forceinline__ void mma16816(float* c, const uint32_t* a, const uint32_t* b) {
    asm volatile("mma.sync.aligned.m16n8k16.row.col.f32.bf16.bf16.f32 "
                 "{%0,%1,%2,%3}, {%4,%5,%6,%7}, {%8,%9}, {%0,%1,%2,%3};"
                 : "+f"(c[0]), "+f"(c[1]), "+f"(c[2]), "+f"(c[3])
                 : "r"(a[0]), "r"(a[1]), "r"(a[2]), "r"(a[3]), "r"(b[0]), "r"(b[1]));
}
#define SW128(off) ((off) ^ (((off) >> 3) & 0x70))

// ============================================================
// Conversion: fp32 -> bf16 hi + bf16 lo (residual)
// ============================================================
__global__ __launch_bounds__(256)
void convA_kernel(const float* __restrict__ X, int which)
{
    int i = (blockIdx.x * 256 + threadIdx.x) * 4;
    float4 x = *(const float4*)(X + i);
    __nv_bfloat16 h0 = __float2bfloat16(x.x);
    __nv_bfloat16 h1 = __float2bfloat16(x.y);
    __nv_bfloat16 h2 = __float2bfloat16(x.z);
    __nv_bfloat16 h3 = __float2bfloat16(x.w);
    __nv_bfloat16 l0 = __float2bfloat16(x.x - __bfloat162float(h0));
    __nv_bfloat16 l1 = __float2bfloat16(x.y - __bfloat162float(h1));
    __nv_bfloat16 l2 = __float2bfloat16(x.z - __bfloat162float(h2));
    __nv_bfloat16 l3 = __float2bfloat16(x.w - __bfloat162float(h3));
    __nv_bfloat162* ph = (__nv_bfloat162*)(&g_Ahi[which][i]);
    __nv_bfloat162* pl = (__nv_bfloat162*)(&g_Alo[which][i]);
    ph[0] = __nv_bfloat162(h0, h1); ph[1] = __nv_bfloat162(h2, h3);
    pl[0] = __nv_bfloat162(l0, l1); pl[1] = __nv_bfloat162(l2, l3);
}

// Transpose W [K=512][N] -> W^T [N][512] in bf16 hi/lo (coalesced both sides)
__global__ __launch_bounds__(256)
void convW_kernel(const float* __restrict__ W, int N, int off)
{
    __shared__ float t[32][33];
    const int k0 = blockIdx.x * 32;
    const int n0 = blockIdx.y * 32;
    const int tx = threadIdx.x & 31;
    const int ty = threadIdx.x >> 5;   // 0..7
    #pragma unroll
    for (int i = ty; i < 32; i += 8)
        t[i][tx] = W[(size_t)(k0 + i) * N + n0 + tx];
    __syncthreads();
    #pragma unroll
    for (int i = ty; i < 32; i += 8) {
        float x = t[tx][i];
        __nv_bfloat16 h = __float2bfloat16(x);
        size_t idx = (size_t)off + (size_t)(n0 + i) * 512 + k0 + tx;
        g_Whi[idx] = h;
        g_Wlo[idx] = __float2bfloat16(x - __bfloat162float(h));
    }
}

// ============================================================
// HMMA projection GEMM (bf16x3 error-corrected):
//   C[8192 x N] = A[8192x512] @ W[512xN] + bias
//   block tile 128(M) x 128(N), K-chunk 64, 8 warps of 64x32.
//   scatter into per-head (B,H,S,D) split buffers.
// ============================================================
#define AH_OFF 0
#define AL_OFF 16384
#define BH_OFF 32768
#define BL_OFF 49152
#define GEMM_SMEM 65536

__global__ __launch_bounds__(256)
void gemm_hmma(int which, int woff, const float* __restrict__ bias, int perHead, int mode)
{
    extern __shared__ __align__(1024) char smem[];
    const uint32_t sbase = smem_u32(smem);
    const int tid = threadIdx.x;
    const int lane = tid & 31;
    const int wid = tid >> 5;
    const int wm = (wid & 1) * 64;    // warp M offset within tile
    const int wn = (wid >> 1) * 32;   // warp N offset within tile

    const int m0 = blockIdx.x * 128;
    const int n0 = blockIdx.y * 128;

    const __nv_bfloat16* Ahi = g_Ahi[which];
    const __nv_bfloat16* Alo = g_Alo[which];
    const __nv_bfloat16* Whi = g_Whi + (size_t)woff;
    const __nv_bfloat16* Wlo = g_Wlo + (size_t)woff;

    float* o0; float* o1; float* o2;
    if (mode == 0)      { o0 = g_q1; o1 = g_q2; o2 = g_gate; }
    else if (mode == 1) { o0 = g_k1; o1 = g_k2; o2 = g_k2; }
    else                { o0 = g_v;  o1 = g_v;  o2 = g_v;  }

    float C[4][4][4];
    #pragma unroll
    for (int i = 0; i < 4; i++)
        #pragma unroll
        for (int j = 0; j < 4; j++)
            #pragma unroll
            for (int c = 0; c < 4; c++) C[i][j][c] = 0.0f;

    // loader indices: 128 rows x 64 bf16 per tile = 1024 x 16B chunks
    const int lrow = tid >> 1;          // 0..127 (2 chunks per thread per iter? no)
    // use: idx = tid + 256*i, row = idx>>3, chunk = idx&7
    for (int kc = 0; kc < 512; kc += 64) {
        #pragma unroll
        for (int i = 0; i < 4; i++) {
            int idx = tid + 256 * i;
            int row = idx >> 3, u = idx & 7;
            uint32_t soff = SW128((uint32_t)(row * 128 + u * 16));
            *(uint4*)(smem + AH_OFF + soff) = *(const uint4*)(Ahi + (size_t)(m0 + row) * 512 + kc + u * 8);
            *(uint4*)(smem + AL_OFF + soff) = *(const uint4*)(Alo + (size_t)(m0 + row) * 512 + kc + u * 8);
            *(uint4*)(smem + BH_OFF + soff) = *(const uint4*)(Whi + (size_t)(n0 + row) * 512 + kc + u * 8);
            *(uint4*)(smem + BL_OFF + soff) = *(const uint4*)(Wlo + (size_t)(n0 + row) * 512 + kc + u * 8);
        }
        __syncthreads();

        #pragma unroll
        for (int ks = 0; ks < 4; ks++) {
            uint32_t ah[4][4], al[4][4];
            #pragma unroll
            for (int mi = 0; mi < 4; mi++) {
                uint32_t off = (uint32_t)((wm + mi * 16 + (lane & 15)) * 128 + ks * 32 + (lane >> 4) * 16);
                off = SW128(off);
                ldsm_x4(ah[mi], sbase + AH_OFF + off);
                ldsm_x4(al[mi], sbase + AL_OFF + off);
            }
            uint32_t bh[4][2], bl[4][2];
            #pragma unroll
            for (int ni = 0; ni < 4; ni++) {
                uint32_t off = (uint32_t)((wn + ni * 8 + (lane & 7)) * 128 + ks * 32 + ((lane >> 3) & 1) * 16);
                off = SW128(off);
                ldsm_x2(bh[ni], sbase + BH_OFF + off);
                ldsm_x2(bl[ni], sbase + BL_OFF + off);
            }
            #pragma unroll
            for (int mi = 0; mi < 4; mi++)
                #pragma unroll
                for (int ni = 0; ni < 4; ni++) {
                    mma16816(C[mi][ni], ah[mi], bh[ni]);
                    mma16816(C[mi][ni], ah[mi], bl[ni]);
                    mma16816(C[mi][ni], al[mi], bh[ni]);
                }
        }
        __syncthreads();
    }

    // epilogue: direct scatter-store with bias
    (void)lrow;
    #pragma unroll
    for (int ni = 0; ni < 4; ni++) {
        const int ng = n0 + wn + ni * 8 + (lane & 3) * 2;
        const int h   = ng / perHead;
        const int r   = ng % perHead;
        const int seg = r >> 6;
        const int d   = r & 63;
        float* dst = (seg == 0) ? o0 : ((seg == 1) ? o1 : o2);
        const float bx = bias[ng], by = bias[ng + 1];
        #pragma unroll
        for (int mi = 0; mi < 4; mi++) {
            int mg = m0 + wm + mi * 16 + (lane >> 2);
            int b1 = mg >> 10, s1 = mg & 1023;
            float2 v0 = { C[mi][ni][0] + bx, C[mi][ni][1] + by };
            *(float2*)(dst + (size_t)((b1 * Hc + h) * Sc + s1) * Dc + d) = v0;
            int mg2 = mg + 8;
            int b2 = mg2 >> 10, s2 = mg2 & 1023;
            float2 v1 = { C[mi][ni][2] + bx, C[mi][ni][3] + by };
            *(float2*)(dst + (size_t)((b2 * Hc + h) * Sc + s2) * Dc + d) = v1;
        }
    }
}

// ============================================================
// Flash-style attention with TWO online softmaxes (unchanged R1)
// ============================================================
#define TS(p, rr, cc) p[(rr)*65 + (cc)]

__global__ __launch_bounds__(256)
void attn_kernel(const float* __restrict__ lam_p)
{
    extern __shared__ float sm[];
    float* Q1s = sm;
    float* Q2s = Q1s + 64*65;
    float* K1s = Q2s + 64*65;
    float* K2s = K1s + 64*65;
    float* Vs  = K2s + 64*65;
    float* S1s = Vs  + 64*65;
    float* S2s = S1s + 64*65;
    float* stm1 = S2s + 64*65;
    float* stl1 = stm1 + 64;
    float* stm2 = stl1 + 64;
    float* stl2 = stm2 + 64;
    float* stsc1 = stl2 + 64;
    float* stsc2 = stsc1 + 64;

    const int q0 = blockIdx.x * 64;
    const int h  = blockIdx.y;
    const int b  = blockIdx.z;
    const int tid = threadIdx.x;
    const int ty = tid >> 4, tx = tid & 15;

    const size_t headOff = (size_t)(b*Hc + h) * Sc * Dc;
    const float* q1g = g_q1 + headOff + (size_t)q0 * Dc;
    const float* q2g = g_q2 + headOff + (size_t)q0 * Dc;
    const float* k1g = g_k1 + headOff;
    const float* k2g = g_k2 + headOff;
    const float* vg  = g_v  + headOff;

    const int lr = tid >> 2;
    const int lc = (tid & 3) * 16;
    #pragma unroll
    for (int c = 0; c < 16; c += 4) {
        float4 v1 = *(const float4*)(q1g + lr*Dc + lc + c);
        TS(Q1s, lr, lc+c+0) = v1.x; TS(Q1s, lr, lc+c+1) = v1.y;
        TS(Q1s, lr, lc+c+2) = v1.z; TS(Q1s, lr, lc+c+3) = v1.w;
        float4 v2 = *(const float4*)(q2g + lr*Dc + lc + c);
        TS(Q2s, lr, lc+c+0) = v2.x; TS(Q2s, lr, lc+c+1) = v2.y;
        TS(Q2s, lr, lc+c+2) = v2.z; TS(Q2s, lr, lc+c+3) = v2.w;
    }
    if (tid < 64) {
        stm1[tid] = -1e30f; stl1[tid] = 0.0f;
        stm2[tid] = -1e30f; stl2[tid] = 0.0f;
    }

    float O1[4][4] = {}, O2[4][4] = {};
    __syncthreads();

    for (int kt = 0; kt < Sc; kt += 64) {
        const float* kp1 = k1g + (size_t)kt * Dc;
        const float* kp2 = k2g + (size_t)kt * Dc;
        const float* vp  = vg  + (size_t)kt * Dc;
        #pragma unroll
        for (int c = 0; c < 16; c += 4) {
            float4 v1 = *(const float4*)(kp1 + lr*Dc + lc + c);
            TS(K1s, lr, lc+c+0) = v1.x; TS(K1s, lr, lc+c+1) = v1.y;
            TS(K1s, lr, lc+c+2) = v1.z; TS(K1s, lr, lc+c+3) = v1.w;
            float4 v2 = *(const float4*)(kp2 + lr*Dc + lc + c);
            TS(K2s, lr, lc+c+0) = v2.x; TS(K2s, lr, lc+c+1) = v2.y;
            TS(K2s, lr, lc+c+2) = v2.z; TS(K2s, lr, lc+c+3) = v2.w;
            float4 v3 = *(const float4*)(vp + lr*Dc + lc + c);
            TS(Vs, lr, lc+c+0) = v3.x; TS(Vs, lr, lc+c+1) = v3.y;
            TS(Vs, lr, lc+c+2) = v3.z; TS(Vs, lr, lc+c+3) = v3.w;
        }
        __syncthreads();

        {
            float s1a[4][4] = {}, s2a[4][4] = {};
            #pragma unroll 4
            for (int dd = 0; dd < 64; dd++) {
                float a1[4], b1[4], a2[4], b2[4];
                #pragma unroll
                for (int i = 0; i < 4; i++) { a1[i] = TS(Q1s, 4*ty+i, dd); a2[i] = TS(Q2s, 4*ty+i, dd); }
                #pragma unroll
                for (int j = 0; j < 4; j++) { b1[j] = TS(K1s, 4*tx+j, dd); b2[j] = TS(K2s, 4*tx+j, dd); }
                #pragma unroll
                for (int i = 0; i < 4; i++)
                    #pragma unroll
                    for (int j = 0; j < 4; j++) {
                        s1a[i][j] += a1[i] * b1[j];
                        s2a[i][j] += a2[i] * b2[j];
                    }
            }
            #pragma unroll
            for (int i = 0; i < 4; i++)
                #pragma unroll
                for (int j = 0; j < 4; j++) {
                    TS(S1s, 4*ty+i, 4*tx+j) = s1a[i][j] * 0.125f;
                    TS(S2s, 4*ty+i, 4*tx+j) = s2a[i][j] * 0.125f;
                }
        }
        __syncthreads();

        {
            const int row  = tid >> 2;
            const int base = (tid & 3) * 16;

            float mx = -1e30f;
            #pragma unroll
            for (int c = 0; c < 16; c++) mx = fmaxf(mx, TS(S1s, row, base+c));
            mx = fmaxf(mx, __shfl_xor_sync(0xffffffffu, mx, 1));
            mx = fmaxf(mx, __shfl_xor_sync(0xffffffffu, mx, 2));
            float mold = stm1[row];
            float mnew = fmaxf(mold, mx);
            float sum = 0.0f;
            #pragma unroll
            for (int c = 0; c < 16; c++) {
                float p = __expf(TS(S1s, row, base+c) - mnew);
                TS(S1s, row, base+c) = p;
                sum += p;
            }
            sum += __shfl_xor_sync(0xffffffffu, sum, 1);
            sum += __shfl_xor_sync(0xffffffffu, sum, 2);
            if ((tid & 3) == 0) {
                float scl = __expf(mold - mnew);
                stsc1[row] = scl;
                stl1[row] = stl1[row] * scl + sum;
                stm1[row] = mnew;
            }

            mx = -1e30f;
            #pragma unroll
            for (int c = 0; c < 16; c++) mx = fmaxf(mx, TS(S2s, row, base+c));
            mx = fmaxf(mx, __shfl_xor_sync(0xffffffffu, mx, 1));
            mx = fmaxf(mx, __shfl_xor_sync(0xffffffffu, mx, 2));
            mold = stm2[row];
            mnew = fmaxf(mold, mx);
            sum = 0.0f;
            #pragma unroll
            for (int c = 0; c < 16; c++) {
                float p = __expf(TS(S2s, row, base+c) - mnew);
                TS(S2s, row, base+c) = p;
                sum += p;
            }
            sum += __shfl_xor_sync(0xffffffffu, sum, 1);
            sum += __shfl_xor_sync(0xffffffffu, sum, 2);
            if ((tid & 3) == 0) {
                float scl = __expf(mold - mnew);
                stsc2[row] = scl;
                stl2[row] = stl2[row] * scl + sum;
                stm2[row] = mnew;
            }
        }
        __syncthreads();

        {
            float f1[4], f2[4];
            #pragma unroll
            for (int i = 0; i < 4; i++) { f1[i] = stsc1[4*ty+i]; f2[i] = stsc2[4*ty+i]; }
            #pragma unroll
            for (int i = 0; i < 4; i++)
                #pragma unroll
                for (int c = 0; c < 4; c++) { O1[i][c] *= f1[i]; O2[i][c] *= f2[i]; }

            #pragma unroll 4
            for (int jj = 0; jj < 64; jj++) {
                float vv[4], p1[4], p2[4];
                #pragma unroll
                for (int c = 0; c < 4; c++) vv[c] = TS(Vs, jj, 4*tx+c);
                #pragma unroll
                for (int i = 0; i < 4; i++) { p1[i] = TS(S1s, 4*ty+i, jj); p2[i] = TS(S2s, 4*ty+i, jj); }
                #pragma unroll
                for (int i = 0; i < 4; i++)
                    #pragma unroll
                    for (int c = 0; c < 4; c++) {
                        O1[i][c] += p1[i] * vv[c];
                        O2[i][c] += p2[i] * vv[c];
                    }
            }
        }
        __syncthreads();
    }

    const float lam = lam_p[0];
    #pragma unroll
    for (int i = 0; i < 4; i++) {
        int rr = 4*ty + i;
        float i1 = 1.0f / stl1[rr];
        float i2 = lam  / stl2[rr];
        int s = q0 + rr;
        float4 v;
        v.x = O1[i][0]*i1 - O2[i][0]*i2;
        v.y = O1[i][1]*i1 - O2[i][1]*i2;
        v.z = O1[i][2]*i1 - O2[i][2]*i2;
        v.w = O1[i][3]*i1 - O2[i][3]*i2;
        *(float4*)(g_attn + (size_t)((b*Sc + s)*Hc + h)*Dc + 4*tx) = v;
    }
}

// ============================================================
// Group statistics (unchanged R1)
// ============================================================
__global__ __launch_bounds__(256)
void stats_kernel()
{
    const int b = blockIdx.x >> 3;
    const int j = blockIdx.x & 7;
    const int tid = threadIdx.x;
    double s = 0.0, sq = 0.0;
    const float* base = g_attn + (size_t)b*Sc*Hc*Dc + j*8;
    for (int t = tid; t < Sc*Hc; t += 256) {
        const float* p = base + (size_t)t * 64;
        #pragma unroll
        for (int i = 0; i < 8; i++) {
            float x = p[i];
            s  += (double)x;
            sq += (double)x * (double)x;
        }
    }
    __shared__ double ss[256], sqq[256];
    ss[tid] = s; sqq[tid] = sq;
    __syncthreads();
    for (int o = 128; o > 0; o >>= 1) {
        if (tid < o) { ss[tid] += ss[tid+o]; sqq[tid] += sqq[tid+o]; }
        __syncthreads();
    }
    if (tid == 0) {
        double mean = ss[0] / 65536.0;
        double var  = sqq[0] / 65536.0 - mean * mean;
        g_mean[blockIdx.x] = (float)mean;
        g_rstd[blockIdx.x] = (float)(1.0 / sqrt(var + 1e-3));
    }
}

// ============================================================
// Final elementwise (unchanged R1)
// ============================================================
__global__ __launch_bounds__(256)
void final_kernel(const float* __restrict__ gamma, const float* __restrict__ beta,
                  const float* __restrict__ li_p, float* __restrict__ out)
{
    const int idx = (blockIdx.x * 256 + threadIdx.x) * 4;
    const int d = idx & 63;
    const int h = (idx >> 6) & 7;
    const int s = (idx >> 9) & 1023;
    const int b = idx >> 19;
    const int j = d >> 3;
    const float mean = g_mean[b*8+j];
    const float rstd = g_rstd[b*8+j];
    const float li = 1.0f - li_p[0];
    float4 a  = *(const float4*)(g_attn + idx);
    float4 g  = *(const float4*)(g_gate + (size_t)((b*Hc+h)*Sc + s)*Dc + d);
    float4 gm = *(const float4*)(gamma + d);
    float4 bt = *(const float4*)(beta + d);
    float4 o;
    o.x = ((a.x-mean)*rstd*gm.x + bt.x) * li * (1.0f/(1.0f+__expf(-g.x)));
    o.y = ((a.y-mean)*rstd*gm.y + bt.y) * li * (1.0f/(1.0f+__expf(-g.y)));
    o.z = ((a.z-mean)*rstd*gm.z + bt.z) * li * (1.0f/(1.0f+__expf(-g.z)));
    o.w = ((a.w-mean)*rstd*gm.w + bt.w) * li * (1.0f/(1.0f+__expf(-g.w)));
    *(float4*)(out + idx) = o;
}

// ============================================================
extern "C" void kernel_launch(void* const* d_in, const int* in_sizes, int n_in,
                              void* d_out, int out_size)
{
    const float* query  = (const float*)d_in[0];
    const float* key    = (const float*)d_in[1];
    const float* values = (const float*)d_in[2];
    const float* Wq = (const float*)d_in[3];
    const float* bq = (const float*)d_in[4];
    const float* Wk = (const float*)d_in[5];
    const float* bk = (const float*)d_in[6];
    const float* Wv = (const float*)d_in[7];
    const float* bv = (const float*)d_in[8];
    const float* gamma = (const float*)d_in[9];
    const float* beta  = (const float*)d_in[10];
    const float* lam   = (const float*)d_in[11];
    const float* lambda_init = (const float*)d_in[12];
    float* out = (float*)d_out;

    const int attn_smem = (7*64*65 + 6*64) * (int)sizeof(float);  // 118016 B
    cudaFuncSetAttribute(attn_kernel, cudaFuncAttributeMaxDynamicSharedMemorySize, attn_smem);
    cudaFuncSetAttribute(gemm_hmma, cudaFuncAttributeMaxDynamicSharedMemorySize, GEMM_SMEM);

    // bf16 hi/lo conversions
    convA_kernel<<<4096, 256>>>(query,  0);
    convA_kernel<<<4096, 256>>>(key,    1);
    convA_kernel<<<4096, 256>>>(values, 2);
    convW_kernel<<<dim3(16, 48), 256>>>(Wq, 1536, 0);
    convW_kernel<<<dim3(16, 32), 256>>>(Wk, 1024, 1536*512);
    convW_kernel<<<dim3(16, 16), 256>>>(Wv,  512, 2560*512);

    // HMMA projection GEMMs (128x128 tiles)
    gemm_hmma<<<dim3(64, 12), 256, GEMM_SMEM>>>(0, 0,        bq, 192, 0);
    gemm_hmma<<<dim3(64,  8), 256, GEMM_SMEM>>>(1, 1536*512, bk, 128, 1);
    gemm_hmma<<<dim3(64,  4), 256, GEMM_SMEM>>>(2, 2560*512, bv,  64, 2);

    attn_kernel<<<dim3(16, 8, 8), 256, attn_smem>>>(lam);
    stats_kernel<<<64, 256>>>();
    final_kernel<<<NTOT/1024, 256>>>(gamma, beta, lambda_init, out);
}

// round 4
// speedup vs baseline: 2.5213x; 1.8427x over previous
#include <cuda_runtime.h>
#include <cuda_bf16.h>
#include <math.h>
#include <stdint.h>

#define Bc 8
#define Sc 1024
#define Hc 8
#define Dc 64
#define DMc 512
#define NTOT (Bc*Hc*Sc*Dc)   // 4,194,304

// ---- scratch (device globals; no allocations allowed) ----
__device__ float g_gate[NTOT];   // (B,H,S,D) fp32
__device__ float g_attn[NTOT];   // (B,S,H,D) fp32
__device__ float g_mean[Bc*8];
__device__ float g_rstd[Bc*8];

// bf16 hi/lo attention operands, (B,H,S,D)
__device__ __align__(16) __nv_bfloat16 g_q1h[NTOT], g_q1l[NTOT];
__device__ __align__(16) __nv_bfloat16 g_q2h[NTOT], g_q2l[NTOT];
__device__ __align__(16) __nv_bfloat16 g_k1h[NTOT], g_k1l[NTOT];
__device__ __align__(16) __nv_bfloat16 g_k2h[NTOT], g_k2l[NTOT];
__device__ __align__(16) __nv_bfloat16 g_vh[NTOT],  g_vl[NTOT];

// bf16 hi/lo split operands for tensor-core projection GEMMs
__device__ __align__(16) __nv_bfloat16 g_Ahi[3][8192*512];
__device__ __align__(16) __nv_bfloat16 g_Alo[3][8192*512];
__device__ __align__(16) __nv_bfloat16 g_Whi[3072*512];   // W^T, [N][K] layout
__device__ __align__(16) __nv_bfloat16 g_Wlo[3072*512];

// ============================================================
// helpers: ldmatrix + mma.sync (bf16, HMMA path — sm_103 baseline)
// ============================================================
__device__ __forceinline__ uint32_t smem_u32(const void* p) {
    uint32_t a;
    asm("{ .reg .u64 t; cvta.to.shared.u64 t, %1; cvt.u32.u64 %0, t; }" : "=r"(a) : "l"(p));
    return a;
}
__device__ __forceinline__ void ldsm_x4(uint32_t* r, uint32_t addr) {
    asm volatile("ldmatrix.sync.aligned.m8n8.x4.shared.b16 {%0,%1,%2,%3}, [%4];"
                 : "=r"(r[0]), "=r"(r[1]), "=r"(r[2]), "=r"(r[3]) : "r"(addr));
}
__device__ __forceinline__ void ldsm_x2(uint32_t* r, uint32_t addr) {
    asm volatile("ldmatrix.sync.aligned.m8n8.x2.shared.b16 {%0,%1}, [%2];"
                 : "=r"(r[0]), "=r"(r[1]) : "r"(addr));
}
__device__ __forceinline__ void ldsm_x2t(uint32_t* r, uint32_t addr) {
    asm volatile("ldmatrix.sync.aligned.m8n8.x2.trans.shared.b16 {%0,%1}, [%2];"
                 : "=r"(r[0]), "=r"(r[1]) : "r"(addr));
}
__device__ __forceinline__ void mma16816(float* c, const uint32_t* a, const uint32_t* b) {
    asm volatile("mma.sync.aligned.m16n8k16.row.col.f32.bf16.bf16.f32 "
                 "{%0,%1,%2,%3}, {%4,%5,%6,%7}, {%8,%9}, {%0,%1,%2,%3};"
                 : "+f"(c[0]), "+f"(c[1]), "+f"(c[2]), "+f"(c[3])
                 : "r"(a[0]), "r"(a[1]), "r"(a[2]), "r"(a[3]), "r"(b[0]), "r"(b[1]));
}
__device__ __forceinline__ void cp_async16(uint32_t sa, const void* g) {
    asm volatile("cp.async.cg.shared.global [%0], [%1], 16;" :: "r"(sa), "l"(g) : "memory");
}
#define SW128(off) ((off) ^ (((off) >> 3) & 0x70))

// ============================================================
// Conversion: fp32 -> bf16 hi + bf16 lo (residual)
// ============================================================
__global__ __launch_bounds__(256)
void convA_kernel(const float* __restrict__ X, int which)
{
    int i = (blockIdx.x * 256 + threadIdx.x) * 4;
    float4 x = *(const float4*)(X + i);
    __nv_bfloat16 h0 = __float2bfloat16(x.x);
    __nv_bfloat16 h1 = __float2bfloat16(x.y);
    __nv_bfloat16 h2 = __float2bfloat16(x.z);
    __nv_bfloat16 h3 = __float2bfloat16(x.w);
    __nv_bfloat16 l0 = __float2bfloat16(x.x - __bfloat162float(h0));
    __nv_bfloat16 l1 = __float2bfloat16(x.y - __bfloat162float(h1));
    __nv_bfloat16 l2 = __float2bfloat16(x.z - __bfloat162float(h2));
    __nv_bfloat16 l3 = __float2bfloat16(x.w - __bfloat162float(h3));
    __nv_bfloat162* ph = (__nv_bfloat162*)(&g_Ahi[which][i]);
    __nv_bfloat162* pl = (__nv_bfloat162*)(&g_Alo[which][i]);
    ph[0] = __nv_bfloat162(h0, h1); ph[1] = __nv_bfloat162(h2, h3);
    pl[0] = __nv_bfloat162(l0, l1); pl[1] = __nv_bfloat162(l2, l3);
}

// Transpose W [K=512][N] -> W^T [N][512] in bf16 hi/lo
__global__ __launch_bounds__(256)
void convW_kernel(const float* __restrict__ W, int N, int off)
{
    __shared__ float t[32][33];
    const int k0 = blockIdx.x * 32;
    const int n0 = blockIdx.y * 32;
    const int tx = threadIdx.x & 31;
    const int ty = threadIdx.x >> 5;
    #pragma unroll
    for (int i = ty; i < 32; i += 8)
        t[i][tx] = W[(size_t)(k0 + i) * N + n0 + tx];
    __syncthreads();
    #pragma unroll
    for (int i = ty; i < 32; i += 8) {
        float x = t[tx][i];
        __nv_bfloat16 h = __float2bfloat16(x);
        size_t idx = (size_t)off + (size_t)(n0 + i) * 512 + k0 + tx;
        g_Whi[idx] = h;
        g_Wlo[idx] = __float2bfloat16(x - __bfloat162float(h));
    }
}

// ============================================================
// HMMA projection GEMM (bf16x3): C[8192 x N] = A @ W + bias
// epilogue emits bf16 hi/lo (q1,q2,k1,k2,v) or fp32 (gate)
// ============================================================
#define AH_OFF 0
#define AL_OFF 16384
#define BH_OFF 32768
#define BL_OFF 49152
#define GEMM_SMEM 65536

__global__ __launch_bounds__(256)
void gemm_hmma(int which, int woff, const float* __restrict__ bias, int perHead, int mode)
{
    extern __shared__ __align__(1024) char smem[];
    const uint32_t sbase = smem_u32(smem);
    const int tid = threadIdx.x;
    const int lane = tid & 31;
    const int wid = tid >> 5;
    const int wm = (wid & 1) * 64;
    const int wn = (wid >> 1) * 32;

    const int m0 = blockIdx.x * 128;
    const int n0 = blockIdx.y * 128;

    const __nv_bfloat16* Ahi = g_Ahi[which];
    const __nv_bfloat16* Alo = g_Alo[which];
    const __nv_bfloat16* Whi = g_Whi + (size_t)woff;
    const __nv_bfloat16* Wlo = g_Wlo + (size_t)woff;

    float C[4][4][4];
    #pragma unroll
    for (int i = 0; i < 4; i++)
        #pragma unroll
        for (int j = 0; j < 4; j++)
            #pragma unroll
            for (int c = 0; c < 4; c++) C[i][j][c] = 0.0f;

    for (int kc = 0; kc < 512; kc += 64) {
        #pragma unroll
        for (int i = 0; i < 4; i++) {
            int idx = tid + 256 * i;
            int row = idx >> 3, u = idx & 7;
            uint32_t soff = SW128((uint32_t)(row * 128 + u * 16));
            *(uint4*)(smem + AH_OFF + soff) = *(const uint4*)(Ahi + (size_t)(m0 + row) * 512 + kc + u * 8);
            *(uint4*)(smem + AL_OFF + soff) = *(const uint4*)(Alo + (size_t)(m0 + row) * 512 + kc + u * 8);
            *(uint4*)(smem + BH_OFF + soff) = *(const uint4*)(Whi + (size_t)(n0 + row) * 512 + kc + u * 8);
            *(uint4*)(smem + BL_OFF + soff) = *(const uint4*)(Wlo + (size_t)(n0 + row) * 512 + kc + u * 8);
        }
        __syncthreads();

        #pragma unroll
        for (int ks = 0; ks < 4; ks++) {
            uint32_t ah[4][4], al[4][4];
            #pragma unroll
            for (int mi = 0; mi < 4; mi++) {
                uint32_t off = (uint32_t)((wm + mi * 16 + (lane & 15)) * 128 + ks * 32 + (lane >> 4) * 16);
                off = SW128(off);
                ldsm_x4(ah[mi], sbase + AH_OFF + off);
                ldsm_x4(al[mi], sbase + AL_OFF + off);
            }
            uint32_t bh[4][2], bl[4][2];
            #pragma unroll
            for (int ni = 0; ni < 4; ni++) {
                uint32_t off = (uint32_t)((wn + ni * 8 + (lane & 7)) * 128 + ks * 32 + ((lane >> 3) & 1) * 16);
                off = SW128(off);
                ldsm_x2(bh[ni], sbase + BH_OFF + off);
                ldsm_x2(bl[ni], sbase + BL_OFF + off);
            }
            #pragma unroll
            for (int mi = 0; mi < 4; mi++)
                #pragma unroll
                for (int ni = 0; ni < 4; ni++) {
                    mma16816(C[mi][ni], ah[mi], bh[ni]);
                    mma16816(C[mi][ni], ah[mi], bl[ni]);
                    mma16816(C[mi][ni], al[mi], bh[ni]);
                }
        }
        __syncthreads();
    }

    // epilogue: scatter-store bf16 hi/lo (or fp32 gate)
    #pragma unroll
    for (int ni = 0; ni < 4; ni++) {
        const int ng = n0 + wn + ni * 8 + (lane & 3) * 2;
        const int hh  = ng / perHead;
        const int r   = ng % perHead;
        const int seg = r >> 6;
        const int d   = r & 63;
        const float bx = bias[ng], by = bias[ng + 1];
        __nv_bfloat16 *ph = 0, *pl = 0; float* pf = 0;
        if (mode == 0) {
            if (seg == 0)      { ph = g_q1h; pl = g_q1l; }
            else if (seg == 1) { ph = g_q2h; pl = g_q2l; }
            else               { pf = g_gate; }
        } else if (mode == 1) {
            if (seg == 0) { ph = g_k1h; pl = g_k1l; }
            else          { ph = g_k2h; pl = g_k2l; }
        } else { ph = g_vh; pl = g_vl; }
        #pragma unroll
        for (int mi = 0; mi < 4; mi++) {
            #pragma unroll
            for (int half = 0; half < 2; half++) {
                int m = m0 + wm + mi * 16 + (lane >> 2) + half * 8;
                int bb = m >> 10, s = m & 1023;
                size_t idx = (size_t)((bb * Hc + hh) * Sc + s) * Dc + d;
                float v0 = C[mi][ni][half * 2 + 0] + bx;
                float v1 = C[mi][ni][half * 2 + 1] + by;
                if (pf) {
                    *(float2*)(pf + idx) = make_float2(v0, v1);
                } else {
                    __nv_bfloat16 h0 = __float2bfloat16(v0), h1 = __float2bfloat16(v1);
                    __nv_bfloat16 l0 = __float2bfloat16(v0 - __bfloat162float(h0));
                    __nv_bfloat16 l1 = __float2bfloat16(v1 - __bfloat162float(h1));
                    *(__nv_bfloat162*)(ph + idx) = __nv_bfloat162(h0, h1);
                    *(__nv_bfloat162*)(pl + idx) = __nv_bfloat162(l0, l1);
                }
            }
        }
    }
}

// ============================================================
// HMMA flash attention, two online softmaxes, bf16x3 EC.
// 64 q-rows per CTA, K-tile 64, cp.async double-buffered K/V.
// ============================================================
#define AQ1H 0
#define AQ1L 8192
#define AQ2H 16384
#define AQ2L 24576
#define AKV0 32768
#define KVSZ 49152
#define AP1H 131072
#define AP1L 139264
#define AP2H 147456
#define AP2L 155648
#define AS1  163840
#define AS2  180480
#define ASTAT 197120
#define ATTN_SMEM 198656

__global__ __launch_bounds__(256)
void attn_hmma(const float* __restrict__ lam_p)
{
    extern __shared__ __align__(1024) char smem[];
    const uint32_t sb = smem_u32(smem);
    const int tid = threadIdx.x;
    const int lane = tid & 31;
    const int w = tid >> 5;
    const int wm = (w & 3) * 16;
    const int wn = (w >> 2) * 32;

    const int q0 = blockIdx.x * 64;
    const int h = blockIdx.y;
    const int b = blockIdx.z;
    const size_t ho = (size_t)(b * Hc + h) * Sc * Dc;

    const __nv_bfloat16* src[6] = { g_k1h + ho, g_k1l + ho, g_k2h + ho,
                                    g_k2l + ho, g_vh + ho, g_vl + ho };

    float* stm1 = (float*)(smem + ASTAT);
    float* stl1 = stm1 + 64;
    float* stm2 = stl1 + 64;
    float* stl2 = stm2 + 64;
    float* stsc1 = stl2 + 64;
    float* stsc2 = stsc1 + 64;

    // load Q tiles (64x64 bf16 x4, swizzled)
    {
        const __nv_bfloat16* qs[4] = { g_q1h + ho + (size_t)q0 * Dc, g_q1l + ho + (size_t)q0 * Dc,
                                       g_q2h + ho + (size_t)q0 * Dc, g_q2l + ho + (size_t)q0 * Dc };
        #pragma unroll
        for (int t = 0; t < 4; t++)
            #pragma unroll
            for (int i = 0; i < 2; i++) {
                int idx = tid + 256 * i;
                int row = idx >> 3, u = idx & 7;
                *(uint4*)(smem + t * 8192 + SW128((uint32_t)(row * 128 + u * 16))) =
                    *(const uint4*)(qs[t] + row * 64 + u * 8);
            }
    }
    if (tid < 64) {
        stm1[tid] = -1e30f; stl1[tid] = 0.0f;
        stm2[tid] = -1e30f; stl2[tid] = 0.0f;
    }

    // prologue: issue K/V loads for kt=0 into buffer 0
    {
        #pragma unroll
        for (int t = 0; t < 6; t++)
            #pragma unroll
            for (int i = 0; i < 2; i++) {
                int idx = tid + 256 * i;
                int row = idx >> 3, u = idx & 7;
                cp_async16(sb + AKV0 + t * 8192 + SW128((uint32_t)(row * 128 + u * 16)),
                           src[t] + (size_t)row * 64 + u * 8);
            }
        asm volatile("cp.async.commit_group;" ::: "memory");
    }

    float O1[4][4], O2[4][4];
    #pragma unroll
    for (int ni = 0; ni < 4; ni++)
        #pragma unroll
        for (int c = 0; c < 4; c++) { O1[ni][c] = 0.0f; O2[ni][c] = 0.0f; }

    float* S1F = (float*)(smem + AS1);
    float* S2F = (float*)(smem + AS2);

    for (int kt = 0; kt < 16; kt++) {
        const uint32_t bufb = AKV0 + (uint32_t)(kt & 1) * KVSZ;
        asm volatile("cp.async.wait_group 0;" ::: "memory");
        __syncthreads();

        // ---- QK^T (both branches, 3-term EC) ----
        float s1[4][4], s2[4][4];
        #pragma unroll
        for (int ni = 0; ni < 4; ni++)
            #pragma unroll
            for (int c = 0; c < 4; c++) { s1[ni][c] = 0.0f; s2[ni][c] = 0.0f; }

        #pragma unroll
        for (int ks = 0; ks < 4; ks++) {
            uint32_t aoff = SW128((uint32_t)((wm + (lane & 15)) * 128 + ks * 32 + (lane >> 4) * 16));
            uint32_t a1h[4], a1l[4], a2h[4], a2l[4];
            ldsm_x4(a1h, sb + AQ1H + aoff); ldsm_x4(a1l, sb + AQ1L + aoff);
            ldsm_x4(a2h, sb + AQ2H + aoff); ldsm_x4(a2l, sb + AQ2L + aoff);
            #pragma unroll
            for (int ni = 0; ni < 4; ni++) {
                uint32_t boff = SW128((uint32_t)((wn + ni * 8 + (lane & 7)) * 128 + ks * 32 + ((lane >> 3) & 1) * 16));
                uint32_t b1h[2], b1l[2], b2h[2], b2l[2];
                ldsm_x2(b1h, sb + bufb + 0     + boff);
                ldsm_x2(b1l, sb + bufb + 8192  + boff);
                ldsm_x2(b2h, sb + bufb + 16384 + boff);
                ldsm_x2(b2l, sb + bufb + 24576 + boff);
                mma16816(s1[ni], a1h, b1h); mma16816(s1[ni], a1h, b1l); mma16816(s1[ni], a1l, b1h);
                mma16816(s2[ni], a2h, b2h); mma16816(s2[ni], a2h, b2l); mma16816(s2[ni], a2l, b2h);
            }
        }
        {
            int r0 = wm + (lane >> 2), r1 = r0 + 8;
            #pragma unroll
            for (int ni = 0; ni < 4; ni++) {
                int cc = wn + ni * 8 + (lane & 3) * 2;
                S1F[r0 * 65 + cc]     = s1[ni][0] * 0.125f;
                S1F[r0 * 65 + cc + 1] = s1[ni][1] * 0.125f;
                S1F[r1 * 65 + cc]     = s1[ni][2] * 0.125f;
                S1F[r1 * 65 + cc + 1] = s1[ni][3] * 0.125f;
                S2F[r0 * 65 + cc]     = s2[ni][0] * 0.125f;
                S2F[r0 * 65 + cc + 1] = s2[ni][1] * 0.125f;
                S2F[r1 * 65 + cc]     = s2[ni][2] * 0.125f;
                S2F[r1 * 65 + cc + 1] = s2[ni][3] * 0.125f;
            }
        }

        // prefetch next K/V tile into other buffer (overlaps softmax+PV)
        if (kt < 15) {
            const uint32_t nb = AKV0 + (uint32_t)((kt + 1) & 1) * KVSZ;
            #pragma unroll
            for (int t = 0; t < 6; t++)
                #pragma unroll
                for (int i = 0; i < 2; i++) {
                    int idx = tid + 256 * i;
                    int row = idx >> 3, u = idx & 7;
                    cp_async16(sb + nb + t * 8192 + SW128((uint32_t)(row * 128 + u * 16)),
                               src[t] + (size_t)((kt + 1) * 64 + row) * 64 + u * 8);
                }
            asm volatile("cp.async.commit_group;" ::: "memory");
        }
        __syncthreads();

        // ---- online softmax (both branches), write P bf16 hi/lo ----
        {
            const int row = tid >> 2;
            const int base = (tid & 3) * 16;

            // branch 1
            float mx = -1e30f;
            #pragma unroll
            for (int c = 0; c < 16; c++) mx = fmaxf(mx, S1F[row * 65 + base + c]);
            mx = fmaxf(mx, __shfl_xor_sync(0xffffffffu, mx, 1));
            mx = fmaxf(mx, __shfl_xor_sync(0xffffffffu, mx, 2));
            float mold = stm1[row];
            float mnew = fmaxf(mold, mx);
            float sum = 0.0f;
            #pragma unroll
            for (int c = 0; c < 16; c += 2) {
                float p0 = __expf(S1F[row * 65 + base + c]     - mnew);
                float p1 = __expf(S1F[row * 65 + base + c + 1] - mnew);
                sum += p0 + p1;
                __nv_bfloat16 h0 = __float2bfloat16(p0), h1 = __float2bfloat16(p1);
                __nv_bfloat16 l0 = __float2bfloat16(p0 - __bfloat162float(h0));
                __nv_bfloat16 l1 = __float2bfloat16(p1 - __bfloat162float(h1));
                uint32_t off = SW128((uint32_t)(row * 128 + (base + c) * 2));
                *(__nv_bfloat162*)(smem + AP1H + off) = __nv_bfloat162(h0, h1);
                *(__nv_bfloat162*)(smem + AP1L + off) = __nv_bfloat162(l0, l1);
            }
            sum += __shfl_xor_sync(0xffffffffu, sum, 1);
            sum += __shfl_xor_sync(0xffffffffu, sum, 2);
            if ((tid & 3) == 0) {
                float scl = __expf(mold - mnew);
                stsc1[row] = scl;
                stl1[row] = stl1[row] * scl + sum;
                stm1[row] = mnew;
            }

            // branch 2
            mx = -1e30f;
            #pragma unroll
            for (int c = 0; c < 16; c++) mx = fmaxf(mx, S2F[row * 65 + base + c]);
            mx = fmaxf(mx, __shfl_xor_sync(0xffffffffu, mx, 1));
            mx = fmaxf(mx, __shfl_xor_sync(0xffffffffu, mx, 2));
            mold = stm2[row];
            mnew = fmaxf(mold, mx);
            sum = 0.0f;
            #pragma unroll
            for (int c = 0; c < 16; c += 2) {
                float p0 = __expf(S2F[row * 65 + base + c]     - mnew);
                float p1 = __expf(S2F[row * 65 + base + c + 1] - mnew);
                sum += p0 + p1;
                __nv_bfloat16 h0 = __float2bfloat16(p0), h1 = __float2bfloat16(p1);
                __nv_bfloat16 l0 = __float2bfloat16(p0 - __bfloat162float(h0));
                __nv_bfloat16 l1 = __float2bfloat16(p1 - __bfloat162float(h1));
                uint32_t off = SW128((uint32_t)(row * 128 + (base + c) * 2));
                *(__nv_bfloat162*)(smem + AP2H + off) = __nv_bfloat162(h0, h1);
                *(__nv_bfloat162*)(smem + AP2L + off) = __nv_bfloat162(l0, l1);
            }
            sum += __shfl_xor_sync(0xffffffffu, sum, 1);
            sum += __shfl_xor_sync(0xffffffffu, sum, 2);
            if ((tid & 3) == 0) {
                float scl = __expf(mold - mnew);
                stsc2[row] = scl;
                stl2[row] = stl2[row] * scl + sum;
                stm2[row] = mnew;
            }
        }
        __syncthreads();

        // ---- rescale O, then O += P V ----
        {
            float fa1 = stsc1[wm + (lane >> 2)], fb1 = stsc1[wm + (lane >> 2) + 8];
            float fa2 = stsc2[wm + (lane >> 2)], fb2 = stsc2[wm + (lane >> 2) + 8];
            #pragma unroll
            for (int ni = 0; ni < 4; ni++) {
                O1[ni][0] *= fa1; O1[ni][1] *= fa1; O1[ni][2] *= fb1; O1[ni][3] *= fb1;
                O2[ni][0] *= fa2; O2[ni][1] *= fa2; O2[ni][2] *= fb2; O2[ni][3] *= fb2;
            }
            #pragma unroll
            for (int ks = 0; ks < 4; ks++) {
                uint32_t aoff = SW128((uint32_t)((wm + (lane & 15)) * 128 + ks * 32 + (lane >> 4) * 16));
                uint32_t p1h[4], p1l[4], p2h[4], p2l[4];
                ldsm_x4(p1h, sb + AP1H + aoff); ldsm_x4(p1l, sb + AP1L + aoff);
                ldsm_x4(p2h, sb + AP2H + aoff); ldsm_x4(p2l, sb + AP2L + aoff);
                #pragma unroll
                for (int ni = 0; ni < 4; ni++) {
                    uint32_t boff = SW128((uint32_t)((ks * 16 + (lane & 15)) * 128 + (wn + ni * 8) * 2));
                    uint32_t bvh[2], bvl[2];
                    ldsm_x2t(bvh, sb + bufb + 32768 + boff);
                    ldsm_x2t(bvl, sb + bufb + 40960 + boff);
                    mma16816(O1[ni], p1h, bvh); mma16816(O1[ni], p1h, bvl); mma16816(O1[ni], p1l, bvh);
                    mma16816(O2[ni], p2h, bvh); mma16816(O2[ni], p2h, bvl); mma16816(O2[ni], p2l, bvh);
                }
            }
        }
        // loop-top syncthreads guards smem reuse
    }
    __syncthreads();

    // ---- combine & store: O = O1/l1 - lam*O2/l2, (B,S,H,D) ----
    const float lam = lam_p[0];
    {
        int r0 = wm + (lane >> 2), r1 = r0 + 8;
        float i1a = 1.0f / stl1[r0], i1b = 1.0f / stl1[r1];
        float i2a = lam  / stl2[r0], i2b = lam  / stl2[r1];
        #pragma unroll
        for (int ni = 0; ni < 4; ni++) {
            int cc = wn + ni * 8 + (lane & 3) * 2;
            int s0 = q0 + r0, s1r = q0 + r1;
            float2 v0 = { O1[ni][0] * i1a - O2[ni][0] * i2a,
                          O1[ni][1] * i1a - O2[ni][1] * i2a };
            float2 v1 = { O1[ni][2] * i1b - O2[ni][2] * i2b,
                          O1[ni][3] * i1b - O2[ni][3] * i2b };
            *(float2*)(g_attn + (size_t)((b * Sc + s0)  * Hc + h) * Dc + cc) = v0;
            *(float2*)(g_attn + (size_t)((b * Sc + s1r) * Hc + h) * Dc + cc) = v1;
        }
    }
}

// ============================================================
// Group statistics (unchanged)
// ============================================================
__global__ __launch_bounds__(256)
void stats_kernel()
{
    const int b = blockIdx.x >> 3;
    const int j = blockIdx.x & 7;
    const int tid = threadIdx.x;
    double s = 0.0, sq = 0.0;
    const float* base = g_attn + (size_t)b*Sc*Hc*Dc + j*8;
    for (int t = tid; t < Sc*Hc; t += 256) {
        const float* p = base + (size_t)t * 64;
        #pragma unroll
        for (int i = 0; i < 8; i++) {
            float x = p[i];
            s  += (double)x;
            sq += (double)x * (double)x;
        }
    }
    __shared__ double ss[256], sqq[256];
    ss[tid] = s; sqq[tid] = sq;
    __syncthreads();
    for (int o = 128; o > 0; o >>= 1) {
        if (tid < o) { ss[tid] += ss[tid+o]; sqq[tid] += sqq[tid+o]; }
        __syncthreads();
    }
    if (tid == 0) {
        double mean = ss[0] / 65536.0;
        double var  = sqq[0] / 65536.0 - mean * mean;
        g_mean[blockIdx.x] = (float)mean;
        g_rstd[blockIdx.x] = (float)(1.0 / sqrt(var + 1e-3));
    }
}

// ============================================================
// Final elementwise (unchanged)
// ============================================================
__global__ __launch_bounds__(256)
void final_kernel(const float* __restrict__ gamma, const float* __restrict__ beta,
                  const float* __restrict__ li_p, float* __restrict__ out)
{
    const int idx = (blockIdx.x * 256 + threadIdx.x) * 4;
    const int d = idx & 63;
    const int h = (idx >> 6) & 7;
    const int s = (idx >> 9) & 1023;
    const int b = idx >> 19;
    const int j = d >> 3;
    const float mean = g_mean[b*8+j];
    const float rstd = g_rstd[b*8+j];
    const float li = 1.0f - li_p[0];
    float4 a  = *(const float4*)(g_attn + idx);
    float4 g  = *(const float4*)(g_gate + (size_t)((b*Hc+h)*Sc + s)*Dc + d);
    float4 gm = *(const float4*)(gamma + d);
    float4 bt = *(const float4*)(beta + d);
    float4 o;
    o.x = ((a.x-mean)*rstd*gm.x + bt.x) * li * (1.0f/(1.0f+__expf(-g.x)));
    o.y = ((a.y-mean)*rstd*gm.y + bt.y) * li * (1.0f/(1.0f+__expf(-g.y)));
    o.z = ((a.z-mean)*rstd*gm.z + bt.z) * li * (1.0f/(1.0f+__expf(-g.z)));
    o.w = ((a.w-mean)*rstd*gm.w + bt.w) * li * (1.0f/(1.0f+__expf(-g.w)));
    *(float4*)(out + idx) = o;
}

// ============================================================
extern "C" void kernel_launch(void* const* d_in, const int* in_sizes, int n_in,
                              void* d_out, int out_size)
{
    const float* query  = (const float*)d_in[0];
    const float* key    = (const float*)d_in[1];
    const float* values = (const float*)d_in[2];
    const float* Wq = (const float*)d_in[3];
    const float* bq = (const float*)d_in[4];
    const float* Wk = (const float*)d_in[5];
    const float* bk = (const float*)d_in[6];
    const float* Wv = (const float*)d_in[7];
    const float* bv = (const float*)d_in[8];
    const float* gamma = (const float*)d_in[9];
    const float* beta  = (const float*)d_in[10];
    const float* lam   = (const float*)d_in[11];
    const float* lambda_init = (const float*)d_in[12];
    float* out = (float*)d_out;

    cudaFuncSetAttribute(gemm_hmma, cudaFuncAttributeMaxDynamicSharedMemorySize, GEMM_SMEM);
    cudaFuncSetAttribute(attn_hmma, cudaFuncAttributeMaxDynamicSharedMemorySize, ATTN_SMEM);

    // bf16 hi/lo conversions
    convA_kernel<<<4096, 256>>>(query,  0);
    convA_kernel<<<4096, 256>>>(key,    1);
    convA_kernel<<<4096, 256>>>(values, 2);
    convW_kernel<<<dim3(16, 48), 256>>>(Wq, 1536, 0);
    convW_kernel<<<dim3(16, 32), 256>>>(Wk, 1024, 1536*512);
    convW_kernel<<<dim3(16, 16), 256>>>(Wv,  512, 2560*512);

    // HMMA projection GEMMs
    gemm_hmma<<<dim3(64, 12), 256, GEMM_SMEM>>>(0, 0,        bq, 192, 0);
    gemm_hmma<<<dim3(64,  8), 256, GEMM_SMEM>>>(1, 1536*512, bk, 128, 1);
    gemm_hmma<<<dim3(64,  4), 256, GEMM_SMEM>>>(2, 2560*512, bv,  64, 2);

    // HMMA flash attention
    attn_hmma<<<dim3(16, 8, 8), 256, ATTN_SMEM>>>(lam);

    stats_kernel<<<64, 256>>>();
    final_kernel<<<NTOT/1024, 256>>>(gamma, beta, lambda_init, out);
}